// round 13
// baseline (speedup 1.0000x reference)
#include <cuda_runtime.h>
#include <math.h>

#define NRAYS   10000
#define NSTEPS  768
#define Zn      32
#define Yn      512
#define Xn      512
#define WPB     8                        // warps (rays) per block
#define NBLK    ((NRAYS + WPB - 1) / WPB)    // 1250

// Per-block partial sums [l1, l2, absrel]. Every block writes its slot each
// launch before any reader -> no init needed.
__device__ float    g_partials[NBLK * 3];
__device__ unsigned g_count = 0;         // reset by the last block each launch

__global__ void __launch_bounds__(WPB * 32)
ray_march_kernel(const float* __restrict__ grid,     // [5,32,512,512] (T,Z,Y,X)
                 const float* __restrict__ origin,   // [5,3]
                 const float* __restrict__ pts,      // [NRAYS,3]
                 const int*   __restrict__ tindex,   // [NRAYS]
                 float*       __restrict__ out)      // [3]
{
    const int warp = threadIdx.x >> 5;
    const int lane = threadIdx.x & 31;
    const int ray  = blockIdx.x * WPB + warp;   // grid sized exactly: always < NRAYS

    // --- per-ray setup ---
    // tindex & pts are independent loads: issue together. origin would be a
    // DEPENDENT load (needs ti) -> instead load all 5 origins unconditionally
    // (15 floats, uniform across all warps, L1-resident) and select via ALU.
    const int   ti = tindex[ray];
    const float pxr = pts[ray * 3 + 0];
    const float pyr = pts[ray * 3 + 1];
    const float pzr = pts[ray * 3 + 2];

    float oxr = 0.f, oyr = 0.f, ozr = 0.f;
    #pragma unroll
    for (int k = 0; k < 5; k++) {
        const float cx = __ldg(&origin[k * 3 + 0]);
        const float cy = __ldg(&origin[k * 3 + 1]);
        const float cz = __ldg(&origin[k * 3 + 2]);
        if (k == ti) { oxr = cx; oyr = cy; ozr = cz; }
    }

    const float ox = (oxr + 51.2f) * 5.0f;
    const float oy = (oyr + 51.2f) * 5.0f;
    const float oz = (ozr + 3.2f)  * 5.0f;
    const float px = (pxr + 51.2f) * 5.0f;
    const float py = (pyr + 51.2f) * 5.0f;
    const float pz = (pzr + 3.2f)  * 5.0f;

    const float dx = px - ox, dy = py - oy, dz = pz - oz;
    const float gt = sqrtf(dx * dx + dy * dy + dz * dz);
    const float inv = 1.0f / fmaxf(gt, 1e-6f);
    const float ux = dx * inv, uy = dy * inv, uz = dz * inv;

    const float* __restrict__ slice = grid + (size_t)ti * (Zn * Yn * Xn);

    // tau for step at param t (relu'd, 0 if OOB); inb out-param.
    auto sample = [&](float t, bool& inb) -> float {
        const int ix = __float2int_rd(ox + ux * t);
        const int iy = __float2int_rd(oy + uy * t);
        const int iz = __float2int_rd(oz + uz * t);
        inb = ((unsigned)ix < (unsigned)Xn) &
              ((unsigned)iy < (unsigned)Yn) &
              ((unsigned)iz < (unsigned)Zn);
        float v = 0.0f;
        if (inb)
            v = fmaxf(__ldg(&slice[((iz * Yn) + iy) * Xn + ix]), 0.0f);
        return v;
    };

    float T     = 1.0f;   // transmittance entering current chunk = exp(-cum)
    float predL = 0.0f;   // per-lane partial of sum(w * t)

    // 64 steps per iteration, SPLIT layout: lane l owns step base+l (a, first
    // sub-chunk) and step base+32+l (b, second). Each LDG instruction's lanes
    // then cover 32 CONSECUTIVE steps -> near-axis rays share 128B lines.
    // With T_min = 3e-7 (tau_stop ~ 15), ~99% of rays finish in ONE iteration.
    for (int base = 0; base < NSTEPS; base += 64) {
        const float ta = (float)(base + lane) + 0.5f;
        const float tb = ta + 32.0f;
        bool inb_a, inb_b;
        const float a = sample(ta, inb_a);   // two independent LDGs in flight
        const float b = sample(tb, inb_b);

        // scan sub-chunk a (steps base..base+31)
        float csa = a;
        #pragma unroll
        for (int off = 1; off < 32; off <<= 1) {
            float v = __shfl_up_sync(0xffffffffu, csa, off);
            if (lane >= off) csa += v;
        }
        const float Sa = __shfl_sync(0xffffffffu, csa, 31);  // total of a

        // scan sub-chunk b (steps base+32..base+63); cum prefix adds Sa
        float csb = b;
        #pragma unroll
        for (int off = 1; off < 32; off <<= 1) {
            float v = __shfl_up_sync(0xffffffffu, csb, off);
            if (lane >= off) csb += v;
        }

        const float Ea0 = __expf(-(csa - a));        // entering step a
        const float Ea1 = __expf(-csa);              // leaving step a
        const float Eb0 = __expf(-(Sa + csb - b));   // entering step b
        const float Eb1 = __expf(-(Sa + csb));       // leaving step b
        // OOB steps: tau=0 -> adjacent E's equal -> zero contribution (exact)
        predL += T * ((Ea0 - Ea1) * ta + (Eb0 - Eb1) * tb);

        T *= __shfl_sync(0xffffffffu, Eb1, 31);      // fold chunk's total tau

        const unsigned bal = __ballot_sync(0xffffffffu, inb_b);
        // Exit when: last step left the box (convex => no re-entry, all later
        // tau == 0, exact) OR T < 3e-7: dropped contribution per ray
        // <= T * t_max ~ 2.3e-4 voxel ~ 5e-5 m, 4 orders under the 1e-3
        // rel-err budget (R12 measured rel_err = 0.0 with this bound).
        if (!((bal >> 31) & 1u) || T < 3e-7f) break;
    }

    // single butterfly reduction of per-lane pred partials
    #pragma unroll
    for (int off = 16; off; off >>= 1)
        predL += __shfl_xor_sync(0xffffffffu, predL, off);

    // --- per-ray loss terms ---
    const float predm = predL * 0.2f;
    const float gtm   = gt * 0.2f;          // always >= 0 -> valid, count = NRAYS
    const float diff  = gtm - predm;
    const float l1 = fabsf(diff);
    const float l2 = diff * diff * 0.5f;
    const float ar = __fdividef(fabsf(diff), fmaxf(gtm, 1e-6f));

    // Per-block reduction across WPB warps.
    __shared__ float s1[WPB], s2[WPB], s3[WPB];
    if (lane == 0) { s1[warp] = l1; s2[warp] = l2; s3[warp] = ar; }
    __syncthreads();
    if (threadIdx.x < 32) {
        float a = (lane < WPB) ? s1[lane] : 0.f;
        float b = (lane < WPB) ? s2[lane] : 0.f;
        float d = (lane < WPB) ? s3[lane] : 0.f;
        #pragma unroll
        for (int off = WPB >> 1; off; off >>= 1) {
            a += __shfl_xor_sync(0xffffffffu, a, off);
            b += __shfl_xor_sync(0xffffffffu, b, off);
            d += __shfl_xor_sync(0xffffffffu, d, off);
        }
        if (lane == 0) {
            g_partials[blockIdx.x * 3 + 0] = a;
            g_partials[blockIdx.x * 3 + 1] = b;
            g_partials[blockIdx.x * 3 + 2] = d;
        }
    }

    // --- last-block final reduction ---
    // Release atomic orders the partial stores without a gpu-scope fence
    // (avoids CCTL.IVALL chip-wide L1D flush from __threadfence).
    __shared__ unsigned s_isLast;
    __syncthreads();                     // all lane-0 stores of this block done
    if (threadIdx.x == 0) {
        unsigned old;
        asm volatile("atom.release.gpu.global.add.u32 %0, [%1], %2;"
                     : "=r"(old) : "l"(&g_count), "r"(1u) : "memory");
        s_isLast = (old == (unsigned)(NBLK - 1));
    }
    __syncthreads();

    if (s_isLast) {
        // Fixed-order strided sums: deterministic regardless of which block
        // executes this. __ldcg reads at L2 (the coherence point).
        float a = 0.f, b = 0.f, d = 0.f;
        for (int i = threadIdx.x; i < NBLK; i += WPB * 32) {
            a += __ldcg(&g_partials[i * 3 + 0]);
            b += __ldcg(&g_partials[i * 3 + 1]);
            d += __ldcg(&g_partials[i * 3 + 2]);
        }
        #pragma unroll
        for (int off = 16; off; off >>= 1) {
            a += __shfl_xor_sync(0xffffffffu, a, off);
            b += __shfl_xor_sync(0xffffffffu, b, off);
            d += __shfl_xor_sync(0xffffffffu, d, off);
        }
        if (lane == 0) { s1[warp] = a; s2[warp] = b; s3[warp] = d; }
        __syncthreads();
        if (threadIdx.x == 0) {
            float ta = 0.f, tb = 0.f, td = 0.f;
            #pragma unroll
            for (int i = 0; i < WPB; i++) { ta += s1[i]; tb += s2[i]; td += s3[i]; }
            const float cnt = (float)NRAYS;
            out[0] = ta / cnt;
            out[1] = tb / cnt;
            out[2] = td / cnt;
            g_count = 0;                 // reset for next graph replay
        }
    }
}

extern "C" void kernel_launch(void* const* d_in, const int* in_sizes, int n_in,
                              void* d_out, int out_size)
{
    const float* grid   = (const float*)d_in[0];   // (1,5,32,512,512) f32
    const float* origin = (const float*)d_in[1];   // (1,5,3) f32
    const float* pts    = (const float*)d_in[2];   // (1,10000,3) f32
    const int*   tidx   = (const int*)d_in[3];     // (1,10000) i32
    float* out = (float*)d_out;                    // 3 floats

    ray_march_kernel<<<NBLK, WPB * 32>>>(grid, origin, pts, tidx, out);
}